// round 15
// baseline (speedup 1.0000x reference)
#include <cuda_runtime.h>
#include <cuda_fp16.h>
#include <math.h>
#include <stdint.h>

#define T_TOKENS 8192
#define D_DIM    1024
#define E_EXP    8
#define H_DIM    512
#define CAP_E    8192                      // fixed per-expert row capacity (max possible)
#define NROWS    (E_EXP * CAP_E)           // 65536
#define MAXMT    64                        // CAP_E / 128

// ---------------- static device scratch ----------------
__device__ int    g_counts[E_EXP];
__device__ int    g_perm_token[NROWS];     // row -> token
__device__ float  g_row_gate[NROWS];       // row -> gate weight
__device__ __half g_xh[(size_t)T_TOKENS * D_DIM];          // 16 MB
__device__ __half g_Hh[(size_t)NROWS * H_DIM];             // 64 MB (fixed segments)
__device__ __half g_w1h[(size_t)E_EXP * D_DIM * H_DIM];    // 8 MB
__device__ __half g_w2h[(size_t)E_EXP * H_DIM * D_DIM];    // 8 MB

// ---------------- PTX helpers ----------------
__device__ __forceinline__ uint32_t smem_u32(const void* p) {
    uint32_t a;
    asm("{ .reg .u64 t; cvta.to.shared.u64 t, %1; cvt.u32.u64 %0, t; }" : "=r"(a) : "l"(p));
    return a;
}
#define CP_ASYNC16(dst, src) \
    asm volatile("cp.async.cg.shared.global [%0], [%1], 16;" :: "r"(dst), "l"(src))
#define CP_COMMIT() asm volatile("cp.async.commit_group;" ::: "memory")
#define CP_WAIT2()  asm volatile("cp.async.wait_group 2;" ::: "memory")

#define LDMATRIX_X4(r0,r1,r2,r3,addr) \
    asm volatile("ldmatrix.sync.aligned.m8n8.x4.shared.b16 {%0,%1,%2,%3}, [%4];" \
        : "=r"(r0), "=r"(r1), "=r"(r2), "=r"(r3) : "r"(addr))
#define LDMATRIX_X4_T(r0,r1,r2,r3,addr) \
    asm volatile("ldmatrix.sync.aligned.m8n8.x4.trans.shared.b16 {%0,%1,%2,%3}, [%4];" \
        : "=r"(r0), "=r"(r1), "=r"(r2), "=r"(r3) : "r"(addr))
#define MMA_16816(c0,c1,c2,c3,a0,a1,a2,a3,b0,b1) \
    asm volatile("mma.sync.aligned.m16n8k16.row.col.f32.f16.f16.f32 " \
        "{%0,%1,%2,%3}, {%4,%5,%6,%7}, {%8,%9}, {%0,%1,%2,%3};" \
        : "+f"(c0), "+f"(c1), "+f"(c2), "+f"(c3) \
        : "r"(a0), "r"(a1), "r"(a2), "r"(a3), "r"(b0), "r"(b1))

// ---------------- zero kernels ----------------
__global__ void zero_counts_kernel() {
    if (threadIdx.x < E_EXP) g_counts[threadIdx.x] = 0;
}
__global__ void zero_out_kernel(float* __restrict__ out) {
    size_t total4 = (size_t)T_TOKENS * D_DIM / 4;
    for (size_t i = (size_t)blockIdx.x * blockDim.x + threadIdx.x; i < total4;
         i += (size_t)gridDim.x * blockDim.x)
        ((float4*)out)[i] = make_float4(0.f, 0.f, 0.f, 0.f);
}

// ---------------- gating (fp32) — direct gate_w loads (L1-resident), no smem staging ----------------
__global__ void gate_kernel(const float* __restrict__ x,
                            const float* __restrict__ gate_w,
                            const float* __restrict__ gate_b) {
    int warp = threadIdx.x >> 5;
    int lane = threadIdx.x & 31;
    int t = blockIdx.x * 8 + warp;
    if (t >= T_TOKENS) return;

    const float* xr = x + (size_t)t * D_DIM;
    float acc[E_EXP];
#pragma unroll
    for (int e = 0; e < E_EXP; e++) acc[e] = 0.f;
#pragma unroll 4
    for (int d = lane; d < D_DIM; d += 32) {
        float xv = xr[d];
        float4 a = __ldg((const float4*)&gate_w[d * E_EXP]);
        float4 b = __ldg((const float4*)&gate_w[d * E_EXP + 4]);
        acc[0] += xv * a.x; acc[1] += xv * a.y; acc[2] += xv * a.z; acc[3] += xv * a.w;
        acc[4] += xv * b.x; acc[5] += xv * b.y; acc[6] += xv * b.z; acc[7] += xv * b.w;
    }
#pragma unroll
    for (int o = 16; o > 0; o >>= 1)
#pragma unroll
        for (int e = 0; e < E_EXP; e++)
            acc[e] += __shfl_down_sync(0xffffffffu, acc[e], o);

    if (lane == 0) {
        float v[E_EXP];
#pragma unroll
        for (int e = 0; e < E_EXP; e++) v[e] = acc[e] + gate_b[e];
        int i0 = 0;
#pragma unroll
        for (int e = 1; e < E_EXP; e++) if (v[e] > v[i0]) i0 = e;
        int i1 = -1;
#pragma unroll
        for (int e = 0; e < E_EXP; e++)
            if (e != i0 && (i1 < 0 || v[e] > v[i1])) i1 = e;
        float e1 = expf(v[i1] - v[i0]);
        float inv = 1.f / (1.f + e1);
        int p0 = atomicAdd(&g_counts[i0], 1);
        int p1 = atomicAdd(&g_counts[i1], 1);
        int r0 = i0 * CAP_E + p0;
        int r1 = i1 * CAP_E + p1;
        g_perm_token[r0] = t; g_row_gate[r0] = inv;
        g_perm_token[r1] = t; g_row_gate[r1] = e1 * inv;
    }
}

// ---------------- fp32 -> fp16 converts ----------------
#define X4  (T_TOKENS * D_DIM / 4)
#define W14 (E_EXP * D_DIM * H_DIM / 4)
#define W24 (E_EXP * H_DIM * D_DIM / 4)
// x + w1 (needed by GEMM1)
__global__ void f2h_xw1_kernel(const float* __restrict__ x,
                               const float* __restrict__ w1) {
    int i = blockIdx.x * blockDim.x + threadIdx.x;
    const float* in;
    __half* out;
    int j;
    if (i < X4)            { in = x;  out = g_xh;  j = i; }
    else if (i < X4 + W14) { in = w1; out = g_w1h; j = i - X4; }
    else return;
    float4 v = ((const float4*)in)[j];
    __half2* o = (__half2*)out + 2 * (size_t)j;
    o[0] = __floats2half2_rn(v.x, v.y);
    o[1] = __floats2half2_rn(v.z, v.w);
}
// w2 (needed only by GEMM2 — overlaps GEMM1)
__global__ void f2h_w2_kernel(const float* __restrict__ w2) {
    int i = blockIdx.x * blockDim.x + threadIdx.x;
    if (i >= W24) return;
    float4 v = ((const float4*)w2)[i];
    __half2* o = (__half2*)g_w2h + 2 * (size_t)i;
    o[0] = __floats2half2_rn(v.x, v.y);
    o[1] = __floats2half2_rn(v.z, v.w);
}

// ---------------- fp16 tensor-core grouped GEMM (R10 mainloop, fixed segments) ----------------
#define SA 40
#define SB 136
#define A_STAGE (128 * SA * 2)
#define B_STAGE (32 * SB * 2)
#define OFF_A   1024
#define OFF_B   (OFF_A + 4 * A_STAGE)
#define GEMM_SMEM (OFF_B + 4 * B_STAGE)   // 76800 B

__device__ __forceinline__ float gelu_exact(float v) {
    return 0.5f * v * (1.0f + erff(v * 0.70710678118654752f));
}

template<int K_TOTAL, bool FIRST>
__global__ void __launch_bounds__(256, 2)
moe_gemm_hmma(const float* __restrict__ bias, float* __restrict__ out)
{
    constexpr int N_TOT = FIRST ? H_DIM : D_DIM;
    constexpr int NIT   = K_TOTAL / 32;

    const __half* __restrict__ Ag = FIRST ? g_xh  : g_Hh;
    const __half* __restrict__ Wh = FIRST ? g_w1h : g_w2h;

    const int e  = blockIdx.x / MAXMT;
    const int mt = blockIdx.x % MAXMT;
    const int cnt = g_counts[e];
    const int m0 = mt * 128;
    if (m0 >= cnt) return;
    const int rowbase = e * CAP_E + m0;
    const int rowlim  = e * CAP_E + cnt - 1;   // last valid row of this expert
    const int n0 = blockIdx.y * 128;

    extern __shared__ __align__(128) char gsm[];
    float* sbias = (float*)gsm;
    uint32_t sb = smem_u32(gsm);

    const int tid  = threadIdx.x;
    const int wid  = tid >> 5;
    const int lane = tid & 31;

    if (tid < 128) sbias[tid] = bias[(size_t)e * N_TOT + n0 + tid];

    int arow_g = rowbase + (tid >> 1);
    if (arow_g > rowlim) arow_g = rowlim;      // clamp inside written segment
    const __half* aptr;
    if (FIRST) aptr = Ag + (size_t)g_perm_token[arow_g] * D_DIM + (tid & 1) * 16;
    else       aptr = Ag + (size_t)arow_g * H_DIM + (tid & 1) * 16;
    const uint32_t a_dst0 = sb + OFF_A + (uint32_t)(tid >> 1) * (SA * 2) + (uint32_t)(tid & 1) * 32;

    const __half* bptr = Wh + ((size_t)e * K_TOTAL + (tid >> 3)) * N_TOT + n0 + (tid & 7) * 16;
    const uint32_t b_dst0 = sb + OFF_B + (uint32_t)(tid >> 3) * (SB * 2) + (uint32_t)(tid & 7) * 32;

#define LOAD_STAGE(pf) do { \
        uint32_t ad = a_dst0 + ((pf) & 3) * A_STAGE; \
        const __half* as_ = aptr + (pf) * 32; \
        CP_ASYNC16(ad, as_); CP_ASYNC16(ad + 16, as_ + 8); \
        uint32_t bd = b_dst0 + ((pf) & 3) * B_STAGE; \
        const __half* bs_ = bptr + (size_t)(pf) * 32 * N_TOT; \
        CP_ASYNC16(bd, bs_); CP_ASYNC16(bd + 16, bs_ + 8); \
    } while (0)

    LOAD_STAGE(0); CP_COMMIT();
    LOAD_STAGE(1); CP_COMMIT();
    LOAD_STAGE(2); CP_COMMIT();

    const int m0w = (wid & 1) * 64;
    const int n0w = (wid >> 1) * 32;

    float c[4][4][4];
#pragma unroll
    for (int mi = 0; mi < 4; mi++)
#pragma unroll
        for (int ni = 0; ni < 4; ni++)
#pragma unroll
            for (int q = 0; q < 4; q++) c[mi][ni][q] = 0.f;

    const uint32_t a_lm = sb + OFF_A
        + (uint32_t)(m0w + (lane & 15)) * (SA * 2) + (uint32_t)(lane >> 4) * 16;
    const uint32_t b_lm = sb + OFF_B
        + (uint32_t)(lane & 15) * (SB * 2)
        + (uint32_t)n0w * 2 + (uint32_t)(lane >> 4) * 16;

    for (int i = 0; i < NIT; ++i) {
        CP_WAIT2();
        __syncthreads();
        // stage (i+3)&3 == (i-1)&3 was fully consumed before the barrier above
        if (i + 3 < NIT) LOAD_STAGE(i + 3);
        CP_COMMIT();

        const uint32_t abuf = a_lm + (i & 3) * A_STAGE;
        const uint32_t bbuf = b_lm + (i & 3) * B_STAGE;
#pragma unroll
        for (int ks = 0; ks < 2; ++ks) {
            uint32_t af[4][4], bf[2][4];
#pragma unroll
            for (int mi = 0; mi < 4; mi++)
                LDMATRIX_X4(af[mi][0], af[mi][1], af[mi][2], af[mi][3],
                            abuf + (uint32_t)(mi * 16) * (SA * 2) + ks * 32);
#pragma unroll
            for (int nj = 0; nj < 2; nj++)
                LDMATRIX_X4_T(bf[nj][0], bf[nj][1], bf[nj][2], bf[nj][3],
                              bbuf + (uint32_t)(ks * 16) * (SB * 2) + nj * 32);
#pragma unroll
            for (int mi = 0; mi < 4; mi++)
#pragma unroll
                for (int ni = 0; ni < 4; ni++) {
                    int nj = ni >> 1, h = ni & 1;
                    MMA_16816(c[mi][ni][0], c[mi][ni][1], c[mi][ni][2], c[mi][ni][3],
                              af[mi][0], af[mi][1], af[mi][2], af[mi][3],
                              bf[nj][h * 2], bf[nj][h * 2 + 1]);
                }
        }
    }
    __syncthreads();

    // ---- epilogue ----
    const int g   = lane >> 2;
    const int tig = lane & 3;
#pragma unroll
    for (int mi = 0; mi < 4; mi++) {
#pragma unroll
        for (int half = 0; half < 2; half++) {
            int rl = m0w + mi * 16 + g + half * 8;
            if (m0 + rl >= cnt) continue;
            int grow = rowbase + rl;
            if (FIRST) {
                __half* dst = g_Hh + (size_t)grow * H_DIM + n0;
#pragma unroll
                for (int ni = 0; ni < 4; ni++) {
                    int col = n0w + ni * 8 + tig * 2;
                    float v0 = c[mi][ni][half * 2 + 0] + sbias[col];
                    float v1 = c[mi][ni][half * 2 + 1] + sbias[col + 1];
                    *(__half2*)(dst + col) = __floats2half2_rn(gelu_exact(v0), gelu_exact(v1));
                }
            } else {
                float gate = g_row_gate[grow];
                int tok = g_perm_token[grow];
                float* dst = out + (size_t)tok * D_DIM + n0;
#pragma unroll
                for (int ni = 0; ni < 4; ni++) {
                    int col = n0w + ni * 8 + tig * 2;
                    float v0 = gate * (c[mi][ni][half * 2 + 0] + sbias[col]);
                    float v1 = gate * (c[mi][ni][half * 2 + 1] + sbias[col + 1]);
                    atomicAdd((float2*)(dst + col), make_float2(v0, v1));
                }
            }
        }
    }
}

// ---------------- launcher: fork-join graph (3 side streams) ----------------
extern "C" void kernel_launch(void* const* d_in, const int* in_sizes, int n_in,
                              void* d_out, int out_size) {
    const float* x      = (const float*)d_in[0];
    const float* gate_w = (const float*)d_in[1];
    const float* gate_b = (const float*)d_in[2];
    const float* w1     = (const float*)d_in[3];
    const float* b1     = (const float*)d_in[4];
    const float* w2     = (const float*)d_in[5];
    const float* b2     = (const float*)d_in[6];
    float* out = (float*)d_out;

    static cudaStream_t s1 = nullptr, s2 = nullptr, s3 = nullptr;
    static cudaEvent_t ev0 = nullptr, ev1 = nullptr, ev2 = nullptr, ev3 = nullptr;
    if (s1 == nullptr) {
        cudaStreamCreateWithFlags(&s1, cudaStreamNonBlocking);
        cudaStreamCreateWithFlags(&s2, cudaStreamNonBlocking);
        cudaStreamCreateWithFlags(&s3, cudaStreamNonBlocking);
        cudaEventCreateWithFlags(&ev0, cudaEventDisableTiming);
        cudaEventCreateWithFlags(&ev1, cudaEventDisableTiming);
        cudaEventCreateWithFlags(&ev2, cudaEventDisableTiming);
        cudaEventCreateWithFlags(&ev3, cudaEventDisableTiming);
        cudaFuncSetAttribute(moe_gemm_hmma<1024, true>,
                             cudaFuncAttributeMaxDynamicSharedMemorySize, GEMM_SMEM);
        cudaFuncSetAttribute(moe_gemm_hmma<512, false>,
                             cudaFuncAttributeMaxDynamicSharedMemorySize, GEMM_SMEM);
    }

    // fork
    cudaEventRecord(ev0, 0);
    cudaStreamWaitEvent(s1, ev0, 0);
    cudaStreamWaitEvent(s2, ev0, 0);
    cudaStreamWaitEvent(s3, ev0, 0);

    // branch A: routing (zero counts -> gate)
    zero_counts_kernel<<<1, 32, 0, s1>>>();
    gate_kernel<<<T_TOKENS / 8, 256, 0, s1>>>(x, gate_w, gate_b);
    cudaEventRecord(ev1, s1);

    // branch B: fp16 conversion of x + w1 (GEMM1 inputs)
    f2h_xw1_kernel<<<(X4 + W14 + 255) / 256, 256, 0, s2>>>(x, w1);
    cudaEventRecord(ev2, s2);

    // branch C: zero output, then fp16 conversion of w2 (GEMM2-only deps;
    // both overlap GEMM1)
    zero_out_kernel<<<1024, 256, 0, s3>>>(out);
    f2h_w2_kernel<<<(W24 + 255) / 256, 256, 0, s3>>>(w2);
    cudaEventRecord(ev3, s3);

    // join A,B -> GEMM1
    cudaStreamWaitEvent(0, ev1, 0);
    cudaStreamWaitEvent(0, ev2, 0);
    moe_gemm_hmma<1024, true><<<dim3(E_EXP * MAXMT, H_DIM / 128), 256, GEMM_SMEM>>>(b1, out);

    // join C -> GEMM2
    cudaStreamWaitEvent(0, ev3, 0);
    moe_gemm_hmma<512, false><<<dim3(E_EXP * MAXMT, D_DIM / 128), 256, GEMM_SMEM>>>(b2, out);
}

// round 16
// speedup vs baseline: 1.0602x; 1.0602x over previous
#include <cuda_runtime.h>
#include <cuda_fp16.h>
#include <math.h>
#include <stdint.h>

#define T_TOKENS 8192
#define D_DIM    1024
#define E_EXP    8
#define H_DIM    512
#define CAP_E    8192                      // fixed per-expert row capacity (max possible)
#define NROWS    (E_EXP * CAP_E)           // 65536
#define MAXMT    64                        // CAP_E / 128

// ---------------- static device scratch ----------------
__device__ int    g_counts[E_EXP];
__device__ int    g_perm_token[NROWS];     // row -> token
__device__ float  g_row_gate[NROWS];       // row -> gate weight
__device__ __half g_xh[(size_t)T_TOKENS * D_DIM];          // 16 MB
__device__ __half g_Hh[(size_t)NROWS * H_DIM];             // 64 MB (fixed segments)
__device__ __half g_w1h[(size_t)E_EXP * D_DIM * H_DIM];    // 8 MB
__device__ __half g_w2h[(size_t)E_EXP * H_DIM * D_DIM];    // 8 MB

// ---------------- PTX helpers ----------------
__device__ __forceinline__ uint32_t smem_u32(const void* p) {
    uint32_t a;
    asm("{ .reg .u64 t; cvta.to.shared.u64 t, %1; cvt.u32.u64 %0, t; }" : "=r"(a) : "l"(p));
    return a;
}
#define CP_ASYNC16(dst, src) \
    asm volatile("cp.async.cg.shared.global [%0], [%1], 16;" :: "r"(dst), "l"(src))
#define CP_COMMIT() asm volatile("cp.async.commit_group;" ::: "memory")
#define CP_WAIT2()  asm volatile("cp.async.wait_group 2;" ::: "memory")

#define LDMATRIX_X4(r0,r1,r2,r3,addr) \
    asm volatile("ldmatrix.sync.aligned.m8n8.x4.shared.b16 {%0,%1,%2,%3}, [%4];" \
        : "=r"(r0), "=r"(r1), "=r"(r2), "=r"(r3) : "r"(addr))
#define LDMATRIX_X4_T(r0,r1,r2,r3,addr) \
    asm volatile("ldmatrix.sync.aligned.m8n8.x4.trans.shared.b16 {%0,%1,%2,%3}, [%4];" \
        : "=r"(r0), "=r"(r1), "=r"(r2), "=r"(r3) : "r"(addr))
#define MMA_16816(c0,c1,c2,c3,a0,a1,a2,a3,b0,b1) \
    asm volatile("mma.sync.aligned.m16n8k16.row.col.f32.f16.f16.f32 " \
        "{%0,%1,%2,%3}, {%4,%5,%6,%7}, {%8,%9}, {%0,%1,%2,%3};" \
        : "+f"(c0), "+f"(c1), "+f"(c2), "+f"(c3) \
        : "r"(a0), "r"(a1), "r"(a2), "r"(a3), "r"(b0), "r"(b1))

// ---------------- zero kernels ----------------
__global__ void zero_counts_kernel() {
    if (threadIdx.x < E_EXP) g_counts[threadIdx.x] = 0;
}
__global__ void zero_out_kernel(float* __restrict__ out) {
    size_t total4 = (size_t)T_TOKENS * D_DIM / 4;
    for (size_t i = (size_t)blockIdx.x * blockDim.x + threadIdx.x; i < total4;
         i += (size_t)gridDim.x * blockDim.x)
        ((float4*)out)[i] = make_float4(0.f, 0.f, 0.f, 0.f);
}

// ---------------- gating (fp32) — smem-staged gate_w, 16 tokens/block ----------------
__global__ void __launch_bounds__(512)
gate_kernel(const float* __restrict__ x,
            const float* __restrict__ gate_w,
            const float* __restrict__ gate_b) {
    __shared__ float sgw[D_DIM * E_EXP];   // 32 KB
    for (int i = threadIdx.x; i < D_DIM * E_EXP / 4; i += blockDim.x)
        ((float4*)sgw)[i] = ((const float4*)gate_w)[i];
    __syncthreads();

    int warp = threadIdx.x >> 5;
    int lane = threadIdx.x & 31;
    int t = blockIdx.x * 16 + warp;
    if (t >= T_TOKENS) return;

    const float* xr = x + (size_t)t * D_DIM;
    float acc[E_EXP];
#pragma unroll
    for (int e = 0; e < E_EXP; e++) acc[e] = 0.f;
    for (int d = lane; d < D_DIM; d += 32) {
        float xv = xr[d];
        float4 a = *(const float4*)&sgw[d * E_EXP];
        float4 b = *(const float4*)&sgw[d * E_EXP + 4];
        acc[0] += xv * a.x; acc[1] += xv * a.y; acc[2] += xv * a.z; acc[3] += xv * a.w;
        acc[4] += xv * b.x; acc[5] += xv * b.y; acc[6] += xv * b.z; acc[7] += xv * b.w;
    }
#pragma unroll
    for (int o = 16; o > 0; o >>= 1)
#pragma unroll
        for (int e = 0; e < E_EXP; e++)
            acc[e] += __shfl_down_sync(0xffffffffu, acc[e], o);

    if (lane == 0) {
        float v[E_EXP];
#pragma unroll
        for (int e = 0; e < E_EXP; e++) v[e] = acc[e] + gate_b[e];
        int i0 = 0;
#pragma unroll
        for (int e = 1; e < E_EXP; e++) if (v[e] > v[i0]) i0 = e;
        int i1 = -1;
#pragma unroll
        for (int e = 0; e < E_EXP; e++)
            if (e != i0 && (i1 < 0 || v[e] > v[i1])) i1 = e;
        float e1 = expf(v[i1] - v[i0]);
        float inv = 1.f / (1.f + e1);
        int p0 = atomicAdd(&g_counts[i0], 1);
        int p1 = atomicAdd(&g_counts[i1], 1);
        int r0 = i0 * CAP_E + p0;
        int r1 = i1 * CAP_E + p1;
        g_perm_token[r0] = t; g_row_gate[r0] = inv;
        g_perm_token[r1] = t; g_row_gate[r1] = e1 * inv;
    }
}

// ---------------- fp32 -> fp16 converts ----------------
#define X4  (T_TOKENS * D_DIM / 4)
#define W14 (E_EXP * D_DIM * H_DIM / 4)
#define W24 (E_EXP * H_DIM * D_DIM / 4)
// x + w1 (needed by GEMM1)
__global__ void f2h_xw1_kernel(const float* __restrict__ x,
                               const float* __restrict__ w1) {
    int i = blockIdx.x * blockDim.x + threadIdx.x;
    const float* in;
    __half* out;
    int j;
    if (i < X4)            { in = x;  out = g_xh;  j = i; }
    else if (i < X4 + W14) { in = w1; out = g_w1h; j = i - X4; }
    else return;
    float4 v = ((const float4*)in)[j];
    __half2* o = (__half2*)out + 2 * (size_t)j;
    o[0] = __floats2half2_rn(v.x, v.y);
    o[1] = __floats2half2_rn(v.z, v.w);
}
// w2 (needed only by GEMM2 — overlaps GEMM1)
__global__ void f2h_w2_kernel(const float* __restrict__ w2) {
    int i = blockIdx.x * blockDim.x + threadIdx.x;
    if (i >= W24) return;
    float4 v = ((const float4*)w2)[i];
    __half2* o = (__half2*)g_w2h + 2 * (size_t)i;
    o[0] = __floats2half2_rn(v.x, v.y);
    o[1] = __floats2half2_rn(v.z, v.w);
}

// ---------------- fp16 tensor-core grouped GEMM (R10 mainloop, fixed segments) ----------------
#define SA 40
#define SB 136
#define A_STAGE (128 * SA * 2)
#define B_STAGE (32 * SB * 2)
#define OFF_A   1024
#define OFF_B   (OFF_A + 4 * A_STAGE)
#define GEMM_SMEM (OFF_B + 4 * B_STAGE)   // 76800 B

__device__ __forceinline__ float gelu_exact(float v) {
    return 0.5f * v * (1.0f + erff(v * 0.70710678118654752f));
}

template<int K_TOTAL, bool FIRST>
__global__ void __launch_bounds__(256, 2)
moe_gemm_hmma(const float* __restrict__ bias, float* __restrict__ out)
{
    constexpr int N_TOT = FIRST ? H_DIM : D_DIM;
    constexpr int NIT   = K_TOTAL / 32;

    const __half* __restrict__ Ag = FIRST ? g_xh  : g_Hh;
    const __half* __restrict__ Wh = FIRST ? g_w1h : g_w2h;

    const int e  = blockIdx.x / MAXMT;
    const int mt = blockIdx.x % MAXMT;
    const int cnt = g_counts[e];
    const int m0 = mt * 128;
    if (m0 >= cnt) return;
    const int rowbase = e * CAP_E + m0;
    const int rowlim  = e * CAP_E + cnt - 1;   // last valid row of this expert
    const int n0 = blockIdx.y * 128;

    extern __shared__ __align__(128) char gsm[];
    float* sbias = (float*)gsm;
    uint32_t sb = smem_u32(gsm);

    const int tid  = threadIdx.x;
    const int wid  = tid >> 5;
    const int lane = tid & 31;

    if (tid < 128) sbias[tid] = bias[(size_t)e * N_TOT + n0 + tid];

    int arow_g = rowbase + (tid >> 1);
    if (arow_g > rowlim) arow_g = rowlim;      // clamp inside written segment
    const __half* aptr;
    if (FIRST) aptr = Ag + (size_t)g_perm_token[arow_g] * D_DIM + (tid & 1) * 16;
    else       aptr = Ag + (size_t)arow_g * H_DIM + (tid & 1) * 16;
    const uint32_t a_dst0 = sb + OFF_A + (uint32_t)(tid >> 1) * (SA * 2) + (uint32_t)(tid & 1) * 32;

    const __half* bptr = Wh + ((size_t)e * K_TOTAL + (tid >> 3)) * N_TOT + n0 + (tid & 7) * 16;
    const uint32_t b_dst0 = sb + OFF_B + (uint32_t)(tid >> 3) * (SB * 2) + (uint32_t)(tid & 7) * 32;

#define LOAD_STAGE(pf) do { \
        uint32_t ad = a_dst0 + ((pf) & 3) * A_STAGE; \
        const __half* as_ = aptr + (pf) * 32; \
        CP_ASYNC16(ad, as_); CP_ASYNC16(ad + 16, as_ + 8); \
        uint32_t bd = b_dst0 + ((pf) & 3) * B_STAGE; \
        const __half* bs_ = bptr + (size_t)(pf) * 32 * N_TOT; \
        CP_ASYNC16(bd, bs_); CP_ASYNC16(bd + 16, bs_ + 8); \
    } while (0)

    LOAD_STAGE(0); CP_COMMIT();
    LOAD_STAGE(1); CP_COMMIT();
    LOAD_STAGE(2); CP_COMMIT();

    const int m0w = (wid & 1) * 64;
    const int n0w = (wid >> 1) * 32;

    float c[4][4][4];
#pragma unroll
    for (int mi = 0; mi < 4; mi++)
#pragma unroll
        for (int ni = 0; ni < 4; ni++)
#pragma unroll
            for (int q = 0; q < 4; q++) c[mi][ni][q] = 0.f;

    const uint32_t a_lm = sb + OFF_A
        + (uint32_t)(m0w + (lane & 15)) * (SA * 2) + (uint32_t)(lane >> 4) * 16;
    const uint32_t b_lm = sb + OFF_B
        + (uint32_t)(lane & 15) * (SB * 2)
        + (uint32_t)n0w * 2 + (uint32_t)(lane >> 4) * 16;

    for (int i = 0; i < NIT; ++i) {
        CP_WAIT2();
        __syncthreads();
        // stage (i+3)&3 == (i-1)&3 was fully consumed before the barrier above
        if (i + 3 < NIT) LOAD_STAGE(i + 3);
        CP_COMMIT();

        const uint32_t abuf = a_lm + (i & 3) * A_STAGE;
        const uint32_t bbuf = b_lm + (i & 3) * B_STAGE;
#pragma unroll
        for (int ks = 0; ks < 2; ++ks) {
            uint32_t af[4][4], bf[2][4];
#pragma unroll
            for (int mi = 0; mi < 4; mi++)
                LDMATRIX_X4(af[mi][0], af[mi][1], af[mi][2], af[mi][3],
                            abuf + (uint32_t)(mi * 16) * (SA * 2) + ks * 32);
#pragma unroll
            for (int nj = 0; nj < 2; nj++)
                LDMATRIX_X4_T(bf[nj][0], bf[nj][1], bf[nj][2], bf[nj][3],
                              bbuf + (uint32_t)(ks * 16) * (SB * 2) + nj * 32);
#pragma unroll
            for (int mi = 0; mi < 4; mi++)
#pragma unroll
                for (int ni = 0; ni < 4; ni++) {
                    int nj = ni >> 1, h = ni & 1;
                    MMA_16816(c[mi][ni][0], c[mi][ni][1], c[mi][ni][2], c[mi][ni][3],
                              af[mi][0], af[mi][1], af[mi][2], af[mi][3],
                              bf[nj][h * 2], bf[nj][h * 2 + 1]);
                }
        }
    }
    __syncthreads();

    // ---- epilogue ----
    const int g   = lane >> 2;
    const int tig = lane & 3;
#pragma unroll
    for (int mi = 0; mi < 4; mi++) {
#pragma unroll
        for (int half = 0; half < 2; half++) {
            int rl = m0w + mi * 16 + g + half * 8;
            if (m0 + rl >= cnt) continue;
            int grow = rowbase + rl;
            if (FIRST) {
                __half* dst = g_Hh + (size_t)grow * H_DIM + n0;
#pragma unroll
                for (int ni = 0; ni < 4; ni++) {
                    int col = n0w + ni * 8 + tig * 2;
                    float v0 = c[mi][ni][half * 2 + 0] + sbias[col];
                    float v1 = c[mi][ni][half * 2 + 1] + sbias[col + 1];
                    *(__half2*)(dst + col) = __floats2half2_rn(gelu_exact(v0), gelu_exact(v1));
                }
            } else {
                float gate = g_row_gate[grow];
                int tok = g_perm_token[grow];
                float* dst = out + (size_t)tok * D_DIM + n0;
#pragma unroll
                for (int ni = 0; ni < 4; ni++) {
                    int col = n0w + ni * 8 + tig * 2;
                    float v0 = gate * (c[mi][ni][half * 2 + 0] + sbias[col]);
                    float v1 = gate * (c[mi][ni][half * 2 + 1] + sbias[col + 1]);
                    atomicAdd((float2*)(dst + col), make_float2(v0, v1));
                }
            }
        }
    }
}

// ---------------- launcher: fork-join graph (3 side streams) ----------------
extern "C" void kernel_launch(void* const* d_in, const int* in_sizes, int n_in,
                              void* d_out, int out_size) {
    const float* x      = (const float*)d_in[0];
    const float* gate_w = (const float*)d_in[1];
    const float* gate_b = (const float*)d_in[2];
    const float* w1     = (const float*)d_in[3];
    const float* b1     = (const float*)d_in[4];
    const float* w2     = (const float*)d_in[5];
    const float* b2     = (const float*)d_in[6];
    float* out = (float*)d_out;

    static cudaStream_t s1 = nullptr, s2 = nullptr, s3 = nullptr;
    static cudaEvent_t ev0 = nullptr, ev1 = nullptr, ev2 = nullptr, ev3 = nullptr;
    if (s1 == nullptr) {
        cudaStreamCreateWithFlags(&s1, cudaStreamNonBlocking);
        cudaStreamCreateWithFlags(&s2, cudaStreamNonBlocking);
        cudaStreamCreateWithFlags(&s3, cudaStreamNonBlocking);
        cudaEventCreateWithFlags(&ev0, cudaEventDisableTiming);
        cudaEventCreateWithFlags(&ev1, cudaEventDisableTiming);
        cudaEventCreateWithFlags(&ev2, cudaEventDisableTiming);
        cudaEventCreateWithFlags(&ev3, cudaEventDisableTiming);
        cudaFuncSetAttribute(moe_gemm_hmma<1024, true>,
                             cudaFuncAttributeMaxDynamicSharedMemorySize, GEMM_SMEM);
        cudaFuncSetAttribute(moe_gemm_hmma<512, false>,
                             cudaFuncAttributeMaxDynamicSharedMemorySize, GEMM_SMEM);
    }

    // fork
    cudaEventRecord(ev0, 0);
    cudaStreamWaitEvent(s1, ev0, 0);
    cudaStreamWaitEvent(s2, ev0, 0);
    cudaStreamWaitEvent(s3, ev0, 0);

    // branch A: routing (zero counts -> gate)
    zero_counts_kernel<<<1, 32, 0, s1>>>();
    gate_kernel<<<T_TOKENS / 16, 512, 0, s1>>>(x, gate_w, gate_b);
    cudaEventRecord(ev1, s1);

    // branch B: fp16 conversion of x + w1 (GEMM1 inputs)
    f2h_xw1_kernel<<<(X4 + W14 + 255) / 256, 256, 0, s2>>>(x, w1);
    cudaEventRecord(ev2, s2);

    // branch C: zero output, then fp16 conversion of w2 (GEMM2-only deps;
    // both overlap GEMM1)
    zero_out_kernel<<<1024, 256, 0, s3>>>(out);
    f2h_w2_kernel<<<(W24 + 255) / 256, 256, 0, s3>>>(w2);
    cudaEventRecord(ev3, s3);

    // join A,B -> GEMM1
    cudaStreamWaitEvent(0, ev1, 0);
    cudaStreamWaitEvent(0, ev2, 0);
    moe_gemm_hmma<1024, true><<<dim3(E_EXP * MAXMT, H_DIM / 128), 256, GEMM_SMEM>>>(b1, out);

    // join C -> GEMM2
    cudaStreamWaitEvent(0, ev3, 0);
    moe_gemm_hmma<512, false><<<dim3(E_EXP * MAXMT, D_DIM / 128), 256, GEMM_SMEM>>>(b2, out);
}

// round 17
// speedup vs baseline: 1.0805x; 1.0191x over previous
#include <cuda_runtime.h>
#include <cuda_fp16.h>
#include <math.h>
#include <stdint.h>

#define T_TOKENS 8192
#define D_DIM    1024
#define E_EXP    8
#define H_DIM    512
#define CAP_E    8192
#define NROWS    (E_EXP * CAP_E)           // 65536
#define MAXMT    64                        // CAP_E / 128
#define E_HALF   4                         // experts per GEMM slice

// ---------------- static device scratch ----------------
__device__ int    g_counts[E_EXP];
__device__ int    g_perm_token[NROWS];
__device__ float  g_row_gate[NROWS];
__device__ __half g_xh[(size_t)T_TOKENS * D_DIM];          // 16 MB
__device__ __half g_Hh[(size_t)NROWS * H_DIM];             // 64 MB (fixed segments)
__device__ __half g_w1h[(size_t)E_EXP * D_DIM * H_DIM];    // 8 MB
__device__ __half g_w2h[(size_t)E_EXP * H_DIM * D_DIM];    // 8 MB

// ---------------- PTX helpers ----------------
__device__ __forceinline__ uint32_t smem_u32(const void* p) {
    uint32_t a;
    asm("{ .reg .u64 t; cvta.to.shared.u64 t, %1; cvt.u32.u64 %0, t; }" : "=r"(a) : "l"(p));
    return a;
}
#define CP_ASYNC16(dst, src) \
    asm volatile("cp.async.cg.shared.global [%0], [%1], 16;" :: "r"(dst), "l"(src))
#define CP_COMMIT() asm volatile("cp.async.commit_group;" ::: "memory")
#define CP_WAIT2()  asm volatile("cp.async.wait_group 2;" ::: "memory")

#define LDMATRIX_X4(r0,r1,r2,r3,addr) \
    asm volatile("ldmatrix.sync.aligned.m8n8.x4.shared.b16 {%0,%1,%2,%3}, [%4];" \
        : "=r"(r0), "=r"(r1), "=r"(r2), "=r"(r3) : "r"(addr))
#define LDMATRIX_X4_T(r0,r1,r2,r3,addr) \
    asm volatile("ldmatrix.sync.aligned.m8n8.x4.trans.shared.b16 {%0,%1,%2,%3}, [%4];" \
        : "=r"(r0), "=r"(r1), "=r"(r2), "=r"(r3) : "r"(addr))
#define MMA_16816(c0,c1,c2,c3,a0,a1,a2,a3,b0,b1) \
    asm volatile("mma.sync.aligned.m16n8k16.row.col.f32.f16.f16.f32 " \
        "{%0,%1,%2,%3}, {%4,%5,%6,%7}, {%8,%9}, {%0,%1,%2,%3};" \
        : "+f"(c0), "+f"(c1), "+f"(c2), "+f"(c3) \
        : "r"(a0), "r"(a1), "r"(a2), "r"(a3), "r"(b0), "r"(b1))

// ---------------- zero kernels ----------------
__global__ void zero_counts_kernel() {
    if (threadIdx.x < E_EXP) g_counts[threadIdx.x] = 0;
}
__global__ void zero_out_kernel(float* __restrict__ out) {
    size_t total4 = (size_t)T_TOKENS * D_DIM / 4;
    for (size_t i = (size_t)blockIdx.x * blockDim.x + threadIdx.x; i < total4;
         i += (size_t)gridDim.x * blockDim.x)
        ((float4*)out)[i] = make_float4(0.f, 0.f, 0.f, 0.f);
}

// ---------------- gating (fp32) — smem-staged gate_w, 16 tokens/block ----------------
__global__ void __launch_bounds__(512)
gate_kernel(const float* __restrict__ x,
            const float* __restrict__ gate_w,
            const float* __restrict__ gate_b) {
    __shared__ float sgw[D_DIM * E_EXP];   // 32 KB
    for (int i = threadIdx.x; i < D_DIM * E_EXP / 4; i += blockDim.x)
        ((float4*)sgw)[i] = ((const float4*)gate_w)[i];
    __syncthreads();

    int warp = threadIdx.x >> 5;
    int lane = threadIdx.x & 31;
    int t = blockIdx.x * 16 + warp;
    if (t >= T_TOKENS) return;

    const float* xr = x + (size_t)t * D_DIM;
    float acc[E_EXP];
#pragma unroll
    for (int e = 0; e < E_EXP; e++) acc[e] = 0.f;
    for (int d = lane; d < D_DIM; d += 32) {
        float xv = xr[d];
        float4 a = *(const float4*)&sgw[d * E_EXP];
        float4 b = *(const float4*)&sgw[d * E_EXP + 4];
        acc[0] += xv * a.x; acc[1] += xv * a.y; acc[2] += xv * a.z; acc[3] += xv * a.w;
        acc[4] += xv * b.x; acc[5] += xv * b.y; acc[6] += xv * b.z; acc[7] += xv * b.w;
    }
#pragma unroll
    for (int o = 16; o > 0; o >>= 1)
#pragma unroll
        for (int e = 0; e < E_EXP; e++)
            acc[e] += __shfl_down_sync(0xffffffffu, acc[e], o);

    if (lane == 0) {
        float v[E_EXP];
#pragma unroll
        for (int e = 0; e < E_EXP; e++) v[e] = acc[e] + gate_b[e];
        int i0 = 0;
#pragma unroll
        for (int e = 1; e < E_EXP; e++) if (v[e] > v[i0]) i0 = e;
        int i1 = -1;
#pragma unroll
        for (int e = 0; e < E_EXP; e++)
            if (e != i0 && (i1 < 0 || v[e] > v[i1])) i1 = e;
        float e1 = expf(v[i1] - v[i0]);
        float inv = 1.f / (1.f + e1);
        int p0 = atomicAdd(&g_counts[i0], 1);
        int p1 = atomicAdd(&g_counts[i1], 1);
        int r0 = i0 * CAP_E + p0;
        int r1 = i1 * CAP_E + p1;
        g_perm_token[r0] = t; g_row_gate[r0] = inv;
        g_perm_token[r1] = t; g_row_gate[r1] = e1 * inv;
    }
}

// ---------------- fp32 -> fp16 converts ----------------
#define X4  (T_TOKENS * D_DIM / 4)
#define W14 (E_EXP * D_DIM * H_DIM / 4)
#define W24 (E_EXP * H_DIM * D_DIM / 4)
__global__ void f2h_xw1_kernel(const float* __restrict__ x,
                               const float* __restrict__ w1) {
    int i = blockIdx.x * blockDim.x + threadIdx.x;
    const float* in;
    __half* out;
    int j;
    if (i < X4)            { in = x;  out = g_xh;  j = i; }
    else if (i < X4 + W14) { in = w1; out = g_w1h; j = i - X4; }
    else return;
    float4 v = ((const float4*)in)[j];
    __half2* o = (__half2*)out + 2 * (size_t)j;
    o[0] = __floats2half2_rn(v.x, v.y);
    o[1] = __floats2half2_rn(v.z, v.w);
}
__global__ void f2h_w2_kernel(const float* __restrict__ w2) {
    int i = blockIdx.x * blockDim.x + threadIdx.x;
    if (i >= W24) return;
    float4 v = ((const float4*)w2)[i];
    __half2* o = (__half2*)g_w2h + 2 * (size_t)i;
    o[0] = __floats2half2_rn(v.x, v.y);
    o[1] = __floats2half2_rn(v.z, v.w);
}

// ---------------- fp16 tensor-core grouped GEMM (expert-sliced launches) ----------------
#define SA 40
#define SB 136
#define A_STAGE (128 * SA * 2)
#define B_STAGE (32 * SB * 2)
#define OFF_A   1024
#define OFF_B   (OFF_A + 4 * A_STAGE)
#define GEMM_SMEM (OFF_B + 4 * B_STAGE)   // 76800 B

__device__ __forceinline__ float gelu_exact(float v) {
    return 0.5f * v * (1.0f + erff(v * 0.70710678118654752f));
}

template<int K_TOTAL, bool FIRST>
__global__ void __launch_bounds__(256, 2)
moe_gemm_hmma(const float* __restrict__ bias, float* __restrict__ out, int e_base)
{
    constexpr int N_TOT = FIRST ? H_DIM : D_DIM;
    constexpr int NIT   = K_TOTAL / 32;

    const __half* __restrict__ Ag = FIRST ? g_xh  : g_Hh;
    const __half* __restrict__ Wh = FIRST ? g_w1h : g_w2h;

    const int e  = e_base + blockIdx.x / MAXMT;
    const int mt = blockIdx.x % MAXMT;
    const int cnt = g_counts[e];
    const int m0 = mt * 128;
    if (m0 >= cnt) return;
    const int rowbase = e * CAP_E + m0;
    const int rowlim  = e * CAP_E + cnt - 1;
    const int n0 = blockIdx.y * 128;

    extern __shared__ __align__(128) char gsm[];
    float* sbias = (float*)gsm;
    uint32_t sb = smem_u32(gsm);

    const int tid  = threadIdx.x;
    const int wid  = tid >> 5;
    const int lane = tid & 31;

    if (tid < 128) sbias[tid] = bias[(size_t)e * N_TOT + n0 + tid];

    int arow_g = rowbase + (tid >> 1);
    if (arow_g > rowlim) arow_g = rowlim;
    const __half* aptr;
    if (FIRST) aptr = Ag + (size_t)g_perm_token[arow_g] * D_DIM + (tid & 1) * 16;
    else       aptr = Ag + (size_t)arow_g * H_DIM + (tid & 1) * 16;
    const uint32_t a_dst0 = sb + OFF_A + (uint32_t)(tid >> 1) * (SA * 2) + (uint32_t)(tid & 1) * 32;

    const __half* bptr = Wh + ((size_t)e * K_TOTAL + (tid >> 3)) * N_TOT + n0 + (tid & 7) * 16;
    const uint32_t b_dst0 = sb + OFF_B + (uint32_t)(tid >> 3) * (SB * 2) + (uint32_t)(tid & 7) * 32;

#define LOAD_STAGE(pf) do { \
        uint32_t ad = a_dst0 + ((pf) & 3) * A_STAGE; \
        const __half* as_ = aptr + (pf) * 32; \
        CP_ASYNC16(ad, as_); CP_ASYNC16(ad + 16, as_ + 8); \
        uint32_t bd = b_dst0 + ((pf) & 3) * B_STAGE; \
        const __half* bs_ = bptr + (size_t)(pf) * 32 * N_TOT; \
        CP_ASYNC16(bd, bs_); CP_ASYNC16(bd + 16, bs_ + 8); \
    } while (0)

    LOAD_STAGE(0); CP_COMMIT();
    LOAD_STAGE(1); CP_COMMIT();
    LOAD_STAGE(2); CP_COMMIT();

    const int m0w = (wid & 1) * 64;
    const int n0w = (wid >> 1) * 32;

    float c[4][4][4];
#pragma unroll
    for (int mi = 0; mi < 4; mi++)
#pragma unroll
        for (int ni = 0; ni < 4; ni++)
#pragma unroll
            for (int q = 0; q < 4; q++) c[mi][ni][q] = 0.f;

    const uint32_t a_lm = sb + OFF_A
        + (uint32_t)(m0w + (lane & 15)) * (SA * 2) + (uint32_t)(lane >> 4) * 16;
    const uint32_t b_lm = sb + OFF_B
        + (uint32_t)(lane & 15) * (SB * 2)
        + (uint32_t)n0w * 2 + (uint32_t)(lane >> 4) * 16;

    for (int i = 0; i < NIT; ++i) {
        CP_WAIT2();
        __syncthreads();
        if (i + 3 < NIT) LOAD_STAGE(i + 3);
        CP_COMMIT();

        const uint32_t abuf = a_lm + (i & 3) * A_STAGE;
        const uint32_t bbuf = b_lm + (i & 3) * B_STAGE;
#pragma unroll
        for (int ks = 0; ks < 2; ++ks) {
            uint32_t af[4][4], bf[2][4];
#pragma unroll
            for (int mi = 0; mi < 4; mi++)
                LDMATRIX_X4(af[mi][0], af[mi][1], af[mi][2], af[mi][3],
                            abuf + (uint32_t)(mi * 16) * (SA * 2) + ks * 32);
#pragma unroll
            for (int nj = 0; nj < 2; nj++)
                LDMATRIX_X4_T(bf[nj][0], bf[nj][1], bf[nj][2], bf[nj][3],
                              bbuf + (uint32_t)(ks * 16) * (SB * 2) + nj * 32);
#pragma unroll
            for (int mi = 0; mi < 4; mi++)
#pragma unroll
                for (int ni = 0; ni < 4; ni++) {
                    int nj = ni >> 1, h = ni & 1;
                    MMA_16816(c[mi][ni][0], c[mi][ni][1], c[mi][ni][2], c[mi][ni][3],
                              af[mi][0], af[mi][1], af[mi][2], af[mi][3],
                              bf[nj][h * 2], bf[nj][h * 2 + 1]);
                }
        }
    }
    __syncthreads();

    // ---- epilogue ----
    const int g   = lane >> 2;
    const int tig = lane & 3;
#pragma unroll
    for (int mi = 0; mi < 4; mi++) {
#pragma unroll
        for (int half = 0; half < 2; half++) {
            int rl = m0w + mi * 16 + g + half * 8;
            if (m0 + rl >= cnt) continue;
            int grow = rowbase + rl;
            if (FIRST) {
                __half* dst = g_Hh + (size_t)grow * H_DIM + n0;
#pragma unroll
                for (int ni = 0; ni < 4; ni++) {
                    int col = n0w + ni * 8 + tig * 2;
                    float v0 = c[mi][ni][half * 2 + 0] + sbias[col];
                    float v1 = c[mi][ni][half * 2 + 1] + sbias[col + 1];
                    *(__half2*)(dst + col) = __floats2half2_rn(gelu_exact(v0), gelu_exact(v1));
                }
            } else {
                float gate = g_row_gate[grow];
                int tok = g_perm_token[grow];
                float* dst = out + (size_t)tok * D_DIM + n0;
#pragma unroll
                for (int ni = 0; ni < 4; ni++) {
                    int col = n0w + ni * 8 + tig * 2;
                    float v0 = gate * (c[mi][ni][half * 2 + 0] + sbias[col]);
                    float v1 = gate * (c[mi][ni][half * 2 + 1] + sbias[col + 1]);
                    atomicAdd((float2*)(dst + col), make_float2(v0, v1));
                }
            }
        }
    }
}

// ---------------- launcher: expert-sliced pipelined fork-join ----------------
extern "C" void kernel_launch(void* const* d_in, const int* in_sizes, int n_in,
                              void* d_out, int out_size) {
    const float* x      = (const float*)d_in[0];
    const float* gate_w = (const float*)d_in[1];
    const float* gate_b = (const float*)d_in[2];
    const float* w1     = (const float*)d_in[3];
    const float* b1     = (const float*)d_in[4];
    const float* w2     = (const float*)d_in[5];
    const float* b2     = (const float*)d_in[6];
    float* out = (float*)d_out;

    static cudaStream_t s1 = nullptr, s2 = nullptr, s3 = nullptr;
    static cudaEvent_t ev0 = nullptr, ev1 = nullptr, ev2 = nullptr, ev3 = nullptr,
                       evA = nullptr, evB = nullptr;
    if (s1 == nullptr) {
        cudaStreamCreateWithFlags(&s1, cudaStreamNonBlocking);
        cudaStreamCreateWithFlags(&s2, cudaStreamNonBlocking);
        cudaStreamCreateWithFlags(&s3, cudaStreamNonBlocking);
        cudaEventCreateWithFlags(&ev0, cudaEventDisableTiming);
        cudaEventCreateWithFlags(&ev1, cudaEventDisableTiming);
        cudaEventCreateWithFlags(&ev2, cudaEventDisableTiming);
        cudaEventCreateWithFlags(&ev3, cudaEventDisableTiming);
        cudaEventCreateWithFlags(&evA, cudaEventDisableTiming);
        cudaEventCreateWithFlags(&evB, cudaEventDisableTiming);
        cudaFuncSetAttribute(moe_gemm_hmma<1024, true>,
                             cudaFuncAttributeMaxDynamicSharedMemorySize, GEMM_SMEM);
        cudaFuncSetAttribute(moe_gemm_hmma<512, false>,
                             cudaFuncAttributeMaxDynamicSharedMemorySize, GEMM_SMEM);
    }

    // fork
    cudaEventRecord(ev0, 0);
    cudaStreamWaitEvent(s1, ev0, 0);
    cudaStreamWaitEvent(s2, ev0, 0);
    cudaStreamWaitEvent(s3, ev0, 0);

    // branch A: routing
    zero_counts_kernel<<<1, 32, 0, s1>>>();
    gate_kernel<<<T_TOKENS / 16, 512, 0, s1>>>(x, gate_w, gate_b);
    cudaEventRecord(ev1, s1);

    // branch B: fp16 conversion of x + w1
    f2h_xw1_kernel<<<(X4 + W14 + 255) / 256, 256, 0, s2>>>(x, w1);
    cudaEventRecord(ev2, s2);

    // branch C: zero output, then fp16 conversion of w2
    zero_out_kernel<<<1024, 256, 0, s3>>>(out);
    f2h_w2_kernel<<<(W24 + 255) / 256, 256, 0, s3>>>(w2);
    cudaEventRecord(ev3, s3);

    // GEMM1 slice a (experts 0-3) on stream 0
    cudaStreamWaitEvent(0, ev1, 0);
    cudaStreamWaitEvent(0, ev2, 0);
    moe_gemm_hmma<1024, true><<<dim3(E_HALF * MAXMT, H_DIM / 128), 256, GEMM_SMEM>>>(b1, out, 0);
    cudaEventRecord(evA, 0);

    // GEMM1 slice b (experts 4-7) on stream 0
    moe_gemm_hmma<1024, true><<<dim3(E_HALF * MAXMT, H_DIM / 128), 256, GEMM_SMEM>>>(b1, out, E_HALF);

    // GEMM2 slice a (experts 0-3) on s2: needs G1a + zero_out/w2; overlaps G1b's tail
    cudaStreamWaitEvent(s2, evA, 0);
    cudaStreamWaitEvent(s2, ev3, 0);
    moe_gemm_hmma<512, false><<<dim3(E_HALF * MAXMT, D_DIM / 128), 256, GEMM_SMEM, s2>>>(b2, out, 0);
    cudaEventRecord(evB, s2);

    // GEMM2 slice b (experts 4-7) on stream 0 (after G1b by stream order)
    cudaStreamWaitEvent(0, ev3, 0);
    moe_gemm_hmma<512, false><<<dim3(E_HALF * MAXMT, D_DIM / 128), 256, GEMM_SMEM>>>(b2, out, E_HALF);

    // join G2a into stream 0
    cudaStreamWaitEvent(0, evB, 0);
}